// round 11
// baseline (speedup 1.0000x reference)
#include <cuda_runtime.h>
#include <cuda_fp16.h>
#include <math.h>
#include <stdint.h>

// ---------------------------------------------------------------------------
// MPWEncoder via mma.sync — fp16 GEMMs (fp32 accum). 256x128 block, 64x64
// warp tile, 1 CTA/SM, BKT=128 (2-stage, ~209KB smem, one barrier per tile),
// double conv1d(k2,s2)+tanh fused into GEMM2's epilogue.
// Dims: BATCH=16384, IN=4096, HID=2048, CNV1=1024, out [16384, 256]
// ---------------------------------------------------------------------------
#define BATCH   16384
#define IN_DIM  4096
#define HID_DIM 2048
#define CNV_DIM 1024
#define OUT_DIM 256

typedef __half f16;

// ------------------------- device scratch (no allocs) ----------------------
__device__ __align__(1024) f16 g_x [(size_t)BATCH * IN_DIM];
__device__ __align__(1024) f16 g_w1[(size_t)HID_DIM * IN_DIM];
__device__ __align__(1024) f16 g_h [(size_t)BATCH * HID_DIM];
__device__ __align__(1024) f16 g_w2[(size_t)CNV_DIM * HID_DIM];
__device__ int g_mask_mode[2];

// ------------------------- PTX helpers -------------------------------------
__device__ __forceinline__ uint32_t smem_u32(const void* p) {
    uint32_t a;
    asm("{ .reg .u64 t; cvta.to.shared.u64 t, %1; cvt.u32.u64 %0, t; }"
        : "=r"(a) : "l"(p));
    return a;
}
__device__ __forceinline__ void cp16(uint32_t dst, const void* src) {
    asm volatile("cp.async.cg.shared.global [%0], [%1], 16;" :: "r"(dst), "l"(src));
}
__device__ __forceinline__ void cp_commit() {
    asm volatile("cp.async.commit_group;" ::: "memory");
}
template <int N>
__device__ __forceinline__ void cp_wait() {
    asm volatile("cp.async.wait_group %0;" :: "n"(N) : "memory");
}
__device__ __forceinline__ void ldsm_x4(uint32_t addr, uint32_t* r) {
    asm volatile("ldmatrix.sync.aligned.m8n8.x4.shared.b16 {%0,%1,%2,%3}, [%4];"
                 : "=r"(r[0]), "=r"(r[1]), "=r"(r[2]), "=r"(r[3]) : "r"(addr));
}
__device__ __forceinline__ void mma16816(float* c, const uint32_t* a, const uint32_t* b) {
    asm volatile(
        "mma.sync.aligned.m16n8k16.row.col.f32.f16.f16.f32 "
        "{%0,%1,%2,%3}, {%4,%5,%6,%7}, {%8,%9}, {%0,%1,%2,%3};"
        : "+f"(c[0]), "+f"(c[1]), "+f"(c[2]), "+f"(c[3])
        : "r"(a[0]), "r"(a[1]), "r"(a[2]), "r"(a[3]), "r"(b[0]), "r"(b[1]));
}

// ------------------------- mask detection + preps ---------------------------
__global__ void detect_mask_mode(const uint32_t* __restrict__ m, int* __restrict__ mode) {
    int floatish = 0, all01 = 1;
    for (int i = 0; i < 256; ++i) {
        uint32_t w = m[i];
        if (w == 0x3F800000u) floatish = 1;
        if (w > 1u) all01 = 0;
    }
    *mode = floatish ? 2 : (all01 ? 1 : 0);
}

__device__ __forceinline__ uint32_t pack_h2(float a, float b) {
    __half2 t = __floats2half2_rn(a, b);
    return *reinterpret_cast<uint32_t*>(&t);
}

__global__ void prep_x_f16(const float* __restrict__ x, f16* __restrict__ out, size_t n4) {
    size_t i = (size_t)blockIdx.x * blockDim.x + threadIdx.x;
    if (i >= n4) return;
    float4 v = ((const float4*)x)[i];
    uint2 o;
    o.x = pack_h2(v.x, v.y);
    o.y = pack_h2(v.z, v.w);
    ((uint2*)out)[i] = o;
}

__global__ void prep_w_f16(const float* __restrict__ w, const void* __restrict__ mask,
                           const int* __restrict__ mode_p,
                           f16* __restrict__ out, size_t n4) {
    size_t i = (size_t)blockIdx.x * blockDim.x + threadIdx.x;
    if (i >= n4) return;
    const int mode = *mode_p;
    float4 v = ((const float4*)w)[i];
    bool m0, m1, m2, m3;
    if (mode == 0) {
        uchar4 mm = ((const uchar4*)mask)[i];
        m0 = mm.x; m1 = mm.y; m2 = mm.z; m3 = mm.w;
    } else if (mode == 1) {
        int4 mm = ((const int4*)mask)[i];
        m0 = mm.x; m1 = mm.y; m2 = mm.z; m3 = mm.w;
    } else {
        float4 mm = ((const float4*)mask)[i];
        m0 = mm.x != 0.f; m1 = mm.y != 0.f; m2 = mm.z != 0.f; m3 = mm.w != 0.f;
    }
    uint2 o;
    o.x = pack_h2(m0 ? v.x : 0.f, m1 ? v.y : 0.f);
    o.y = pack_h2(m2 ? v.z : 0.f, m3 ? v.w : 0.f);
    ((uint2*)out)[i] = o;
}

// ------------------------- mma.sync GEMM ------------------------------------
// C[M,N] = tanh(A[M,K] @ B[N,K]^T + bias[N]); A,B fp16, fp32 accumulate.
// Block tile 256x128x128, 8 warps (warp tile 64x64), 2-stage cp.async
// pipeline, ONE __syncthreads per k-tile. Rows padded to 272B: bank(r,u) =
// (68r+4u) mod 32 == (4r+4u) -> each ldsm phase (8 rows, fixed u) covers all
// 32 banks once. MODE 0: fp16 C out. MODE 1: fused double conv -> fp32 out.
#define BMT 256
#define BNT 128
#define BKT 128
#define ROWB 272                           // 256B data + 16B pad per row
#define A_BYTES (BMT * ROWB)               // 69632
#define B_BYTES (BNT * ROWB)               // 34816
#define STAGE_BYTES (A_BYTES + B_BYTES)    // 104448
#define NSTAGE 2
#define SMEM_GEMM (NSTAGE * STAGE_BYTES)   // 208896

__device__ __forceinline__ void load_stage(uint32_t sb,
                                           const f16* A, const f16* B,
                                           int m0, int n0, int k0, int K, int tid) {
#pragma unroll
    for (int i = 0; i < 16; ++i) {         // A: 256 rows x 16 16B-chunks
        const int ch = tid + (i << 8);
        const int row = ch >> 4, u = ch & 15;
        cp16(sb + row * ROWB + u * 16, A + (size_t)(m0 + row) * K + k0 + u * 8);
    }
#pragma unroll
    for (int i = 0; i < 8; ++i) {          // B: 128 rows x 16 16B-chunks
        const int ch = tid + (i << 8);
        const int row = ch >> 4, u = ch & 15;
        cp16(sb + A_BYTES + row * ROWB + u * 16, B + (size_t)(n0 + row) * K + k0 + u * 8);
    }
}

template <int MODE>   // 0: fp16 out; 1: fused conv -> fp32 out
__global__ __launch_bounds__(256, 1)
void gemm_mma(const f16* __restrict__ A, const f16* __restrict__ B,
              const float* __restrict__ bias,
              f16* __restrict__ Ch, float* __restrict__ Cf,
              const float* __restrict__ wc1, const float* __restrict__ bc1,
              const float* __restrict__ wc2, const float* __restrict__ bc2,
              int M, int N, int K) {
    extern __shared__ __align__(128) char smem[];
    const uint32_t sbase = smem_u32(smem);
    const int tid = threadIdx.x;
    const int wid = tid >> 5;
    const int lane = tid & 31;
    const int warp_m = wid >> 1;           // 0..3 -> 64-row slice
    const int warp_n = wid & 1;            // 0..1 -> 64-col slice
    const int m0 = blockIdx.y * BMT;
    const int n0 = blockIdx.x * BNT;

    float acc[4][8][4];
#pragma unroll
    for (int a = 0; a < 4; ++a)
#pragma unroll
        for (int b = 0; b < 8; ++b)
#pragma unroll
            for (int d = 0; d < 4; ++d) acc[a][b][d] = 0.0f;

    const int aRow = warp_m * 64 + (lane & 7) + (((lane >> 3) & 1) << 3);
    const int aUsel = lane >> 4;           // 0/1
    const int bRow = warp_n * 64 + ((lane >> 4) << 3) + (lane & 7);
    const int bUsel = (lane >> 3) & 1;     // 0/1

    const int T = K / BKT;
    load_stage(sbase, A, B, m0, n0, 0, K, tid);
    cp_commit();

    for (int t = 0; t < T; ++t) {
        cp_wait<0>();
        __syncthreads();   // the ONLY barrier per tile

        // loads for stage t+1 target buffer (t+1)&1, whose consumers (iter
        // t-1's compute) are all past the barrier above.
        if (t + 1 < T) {
            load_stage(sbase + ((t + 1) & 1) * STAGE_BYTES, A, B,
                       m0, n0, (t + 1) * BKT, K, tid);
            cp_commit();
        }

        const uint32_t aB = sbase + (t & 1) * STAGE_BYTES;
        const uint32_t bB = aB + A_BYTES;

#pragma unroll
        for (int kk = 0; kk < 8; ++kk) {   // 8 x K=16 steps
            uint32_t ah[4][4];
#pragma unroll
            for (int mf = 0; mf < 4; ++mf) {
                const int m = aRow + mf * 16;
                const int u = kk * 2 + aUsel;
                ldsm_x4(aB + m * ROWB + u * 16, ah[mf]);
            }
#pragma unroll
            for (int nfp = 0; nfp < 4; ++nfp) {
                const int n = bRow + nfp * 16;
                const int u = kk * 2 + bUsel;
                uint32_t bh[4];
                ldsm_x4(bB + n * ROWB + u * 16, bh);   // [n][k] == col-major B
#pragma unroll
                for (int mf = 0; mf < 4; ++mf) {
                    mma16816(acc[mf][2 * nfp],     ah[mf], bh);
                    mma16816(acc[mf][2 * nfp + 1], ah[mf], bh + 2);
                }
            }
        }
    }

    // ----------------- epilogue ---------------------------------------------
    const int gid = lane >> 2, tg = lane & 3;
    float cw10 = 0.f, cw11 = 0.f, cw20 = 0.f, cw21 = 0.f, cb1 = 0.f, cb2 = 0.f;
    if (MODE == 1) {
        cw10 = wc1[0]; cw11 = wc1[1];
        cw20 = wc2[0]; cw21 = wc2[1];
        cb1 = bc1[0];  cb2 = bc2[0];
    }
#pragma unroll
    for (int mf = 0; mf < 4; ++mf) {
#pragma unroll
        for (int nf = 0; nf < 8; ++nf) {
            const int row0 = m0 + warp_m * 64 + mf * 16 + gid;
            const int col = n0 + warp_n * 64 + nf * 8 + tg * 2;
            const float bv0 = bias[col], bv1 = bias[col + 1];
            const float* a4 = acc[mf][nf];
            const float v00 = tanhf(a4[0] + bv0);
            const float v01 = tanhf(a4[1] + bv1);
            const float v10 = tanhf(a4[2] + bv0);
            const float v11 = tanhf(a4[3] + bv1);
            if (MODE == 0) {
                uint32_t* ChW = (uint32_t*)Ch;
                ChW[(size_t)row0 * (N >> 1) + (col >> 1)]       = pack_h2(v00, v01);
                ChW[(size_t)(row0 + 8) * (N >> 1) + (col >> 1)] = pack_h2(v10, v11);
            } else {
                // conv1 over this thread's own (col, col+1) pair
                const float t0 = tanhf(fmaf(v00, cw10, fmaf(v01, cw11, cb1)));
                const float t1 = tanhf(fmaf(v10, cw10, fmaf(v11, cw11, cb1)));
                // conv2 pairs conv1 outputs of tg and tg^1
                const float p0 = __shfl_xor_sync(0xFFFFFFFFu, t0, 1);
                const float p1 = __shfl_xor_sync(0xFFFFFFFFu, t1, 1);
                if ((tg & 1) == 0) {
                    const int j2 = (n0 >> 2) + warp_n * 16 + nf * 2 + (tg >> 1);
                    Cf[(size_t)row0 * OUT_DIM + j2] =
                        tanhf(fmaf(t0, cw20, fmaf(p0, cw21, cb2)));
                    Cf[(size_t)(row0 + 8) * OUT_DIM + j2] =
                        tanhf(fmaf(t1, cw20, fmaf(p1, cw21, cb2)));
                }
            }
        }
    }
}

// ------------------------- launch ------------------------------------------
extern "C" void kernel_launch(void* const* d_in, const int* in_sizes, int n_in,
                              void* d_out, int out_size) {
    const float* x       = (const float*)d_in[0];
    const void*  mask_ih = d_in[1];
    const void*  mask_hc = d_in[2];
    const float* w_ih    = (const float*)d_in[3];
    const float* b_ih    = (const float*)d_in[4];
    const float* w_hc    = (const float*)d_in[5];
    const float* b_hc    = (const float*)d_in[6];
    const float* w_c1    = (const float*)d_in[7];
    const float* b_c1    = (const float*)d_in[8];
    const float* w_c2    = (const float*)d_in[9];
    const float* b_c2    = (const float*)d_in[10];
    float* out = (float*)d_out;

    f16 *xh, *w1, *h, *w2;
    int* mode;
    cudaGetSymbolAddress((void**)&xh, g_x);
    cudaGetSymbolAddress((void**)&w1, g_w1);
    cudaGetSymbolAddress((void**)&h, g_h);
    cudaGetSymbolAddress((void**)&w2, g_w2);
    cudaGetSymbolAddress((void**)&mode, g_mask_mode);

    cudaFuncSetAttribute(gemm_mma<0>, cudaFuncAttributeMaxDynamicSharedMemorySize, SMEM_GEMM);
    cudaFuncSetAttribute(gemm_mma<1>, cudaFuncAttributeMaxDynamicSharedMemorySize, SMEM_GEMM);

    // 0) mask dtype detection
    detect_mask_mode<<<1, 1>>>((const uint32_t*)mask_ih, mode + 0);
    detect_mask_mode<<<1, 1>>>((const uint32_t*)mask_hc, mode + 1);

    // 1) preps: x -> fp16; masked w1/w2 -> fp16
    {
        size_t n4 = (size_t)BATCH * IN_DIM / 4;
        prep_x_f16<<<(unsigned)((n4 + 255) / 256), 256>>>(x, xh, n4);
    }
    {
        size_t n4 = (size_t)HID_DIM * IN_DIM / 4;
        prep_w_f16<<<(unsigned)((n4 + 255) / 256), 256>>>(w_ih, mask_ih, mode + 0, w1, n4);
    }
    {
        size_t n4 = (size_t)CNV_DIM * HID_DIM / 4;
        prep_w_f16<<<(unsigned)((n4 + 255) / 256), 256>>>(w_hc, mask_hc, mode + 1, w2, n4);
    }

    // 2) h = tanh(x @ w1^T + b_ih) -> fp16
    {
        dim3 grid(HID_DIM / BNT, BATCH / BMT);   // (16, 64)
        gemm_mma<0><<<grid, 256, SMEM_GEMM>>>(xh, w1, b_ih, h, nullptr,
                                              nullptr, nullptr, nullptr, nullptr,
                                              BATCH, HID_DIM, IN_DIM);
    }

    // 3) out = tanh(conv2(tanh(conv1(tanh(h @ w2^T + b_hc)))))  (fused)
    {
        dim3 grid(CNV_DIM / BNT, BATCH / BMT);   // (8, 64)
        gemm_mma<1><<<grid, 256, SMEM_GEMM>>>(h, w2, b_hc, nullptr, out,
                                              w_c1, b_c1, w_c2, b_c2,
                                              BATCH, CNV_DIM, HID_DIM);
    }
}

// round 12
// speedup vs baseline: 1.4636x; 1.4636x over previous
#include <cuda_runtime.h>
#include <cuda_fp16.h>
#include <math.h>
#include <stdint.h>

// ---------------------------------------------------------------------------
// MPWEncoder via mma.sync — fp16 GEMMs (fp32 accum). Round-10 winning shape
// (256x128 block, 64x64 warp tile, BKT=64, 1 barrier/tile) deepened to a
// 4-stage cp.async pipeline (221KB smem). Double conv fused in GEMM2 epilogue.
// Dims: BATCH=16384, IN=4096, HID=2048, CNV1=1024, out [16384, 256]
// ---------------------------------------------------------------------------
#define BATCH   16384
#define IN_DIM  4096
#define HID_DIM 2048
#define CNV_DIM 1024
#define OUT_DIM 256

typedef __half f16;

// ------------------------- device scratch (no allocs) ----------------------
__device__ __align__(1024) f16 g_x [(size_t)BATCH * IN_DIM];
__device__ __align__(1024) f16 g_w1[(size_t)HID_DIM * IN_DIM];
__device__ __align__(1024) f16 g_h [(size_t)BATCH * HID_DIM];
__device__ __align__(1024) f16 g_w2[(size_t)CNV_DIM * HID_DIM];
__device__ int g_mask_mode[2];

// ------------------------- PTX helpers -------------------------------------
__device__ __forceinline__ uint32_t smem_u32(const void* p) {
    uint32_t a;
    asm("{ .reg .u64 t; cvta.to.shared.u64 t, %1; cvt.u32.u64 %0, t; }"
        : "=r"(a) : "l"(p));
    return a;
}
__device__ __forceinline__ void cp16(uint32_t dst, const void* src) {
    asm volatile("cp.async.cg.shared.global [%0], [%1], 16;" :: "r"(dst), "l"(src));
}
__device__ __forceinline__ void cp_commit() {
    asm volatile("cp.async.commit_group;" ::: "memory");
}
template <int N>
__device__ __forceinline__ void cp_wait() {
    asm volatile("cp.async.wait_group %0;" :: "n"(N) : "memory");
}
__device__ __forceinline__ void ldsm_x4(uint32_t addr, uint32_t* r) {
    asm volatile("ldmatrix.sync.aligned.m8n8.x4.shared.b16 {%0,%1,%2,%3}, [%4];"
                 : "=r"(r[0]), "=r"(r[1]), "=r"(r[2]), "=r"(r[3]) : "r"(addr));
}
__device__ __forceinline__ void mma16816(float* c, const uint32_t* a, const uint32_t* b) {
    asm volatile(
        "mma.sync.aligned.m16n8k16.row.col.f32.f16.f16.f32 "
        "{%0,%1,%2,%3}, {%4,%5,%6,%7}, {%8,%9}, {%0,%1,%2,%3};"
        : "+f"(c[0]), "+f"(c[1]), "+f"(c[2]), "+f"(c[3])
        : "r"(a[0]), "r"(a[1]), "r"(a[2]), "r"(a[3]), "r"(b[0]), "r"(b[1]));
}

// ------------------------- mask detection + preps ---------------------------
__global__ void detect_mask_mode(const uint32_t* __restrict__ m, int* __restrict__ mode) {
    int floatish = 0, all01 = 1;
    for (int i = 0; i < 256; ++i) {
        uint32_t w = m[i];
        if (w == 0x3F800000u) floatish = 1;
        if (w > 1u) all01 = 0;
    }
    *mode = floatish ? 2 : (all01 ? 1 : 0);
}

__device__ __forceinline__ uint32_t pack_h2(float a, float b) {
    __half2 t = __floats2half2_rn(a, b);
    return *reinterpret_cast<uint32_t*>(&t);
}

__global__ void prep_x_f16(const float* __restrict__ x, f16* __restrict__ out, size_t n4) {
    size_t i = (size_t)blockIdx.x * blockDim.x + threadIdx.x;
    if (i >= n4) return;
    float4 v = ((const float4*)x)[i];
    uint2 o;
    o.x = pack_h2(v.x, v.y);
    o.y = pack_h2(v.z, v.w);
    ((uint2*)out)[i] = o;
}

__global__ void prep_w_f16(const float* __restrict__ w, const void* __restrict__ mask,
                           const int* __restrict__ mode_p,
                           f16* __restrict__ out, size_t n4) {
    size_t i = (size_t)blockIdx.x * blockDim.x + threadIdx.x;
    if (i >= n4) return;
    const int mode = *mode_p;
    float4 v = ((const float4*)w)[i];
    bool m0, m1, m2, m3;
    if (mode == 0) {
        uchar4 mm = ((const uchar4*)mask)[i];
        m0 = mm.x; m1 = mm.y; m2 = mm.z; m3 = mm.w;
    } else if (mode == 1) {
        int4 mm = ((const int4*)mask)[i];
        m0 = mm.x; m1 = mm.y; m2 = mm.z; m3 = mm.w;
    } else {
        float4 mm = ((const float4*)mask)[i];
        m0 = mm.x != 0.f; m1 = mm.y != 0.f; m2 = mm.z != 0.f; m3 = mm.w != 0.f;
    }
    uint2 o;
    o.x = pack_h2(m0 ? v.x : 0.f, m1 ? v.y : 0.f);
    o.y = pack_h2(m2 ? v.z : 0.f, m3 ? v.w : 0.f);
    ((uint2*)out)[i] = o;
}

// ------------------------- mma.sync GEMM ------------------------------------
// C[M,N] = tanh(A[M,K] @ B[N,K]^T + bias[N]); A,B fp16, fp32 accumulate.
// Block tile 256x128x64, 8 warps (warp tile 64x64), 4-stage cp.async pipeline,
// ONE __syncthreads per k-tile (loads for t+3 issued after barrier t, so the
// reused buffer (t-1)%4 is provably drained). ROWB=144 -> conflict-free ldsm.
// MODE 0: fp16 C out.  MODE 1: fused double conv1d(k2,s2)+tanh -> fp32 out.
#define BMT 256
#define BNT 128
#define BKT 64
#define ROWB 144                           // 128B data + 16B pad per row
#define A_BYTES (BMT * ROWB)               // 36864
#define B_BYTES (BNT * ROWB)               // 18432
#define STAGE_BYTES (A_BYTES + B_BYTES)    // 55296
#define NSTAGE 4
#define SMEM_GEMM (NSTAGE * STAGE_BYTES)   // 221184

__device__ __forceinline__ void load_stage(uint32_t sb,
                                           const f16* A, const f16* B,
                                           int m0, int n0, int k0, int K, int tid) {
#pragma unroll
    for (int i = 0; i < 8; ++i) {          // A: 256 rows x 8 16B-chunks
        const int ch = tid + (i << 8);
        const int row = ch >> 3, u = ch & 7;
        cp16(sb + row * ROWB + u * 16, A + (size_t)(m0 + row) * K + k0 + u * 8);
    }
#pragma unroll
    for (int i = 0; i < 4; ++i) {          // B: 128 rows x 8 16B-chunks
        const int ch = tid + (i << 8);
        const int row = ch >> 3, u = ch & 7;
        cp16(sb + A_BYTES + row * ROWB + u * 16, B + (size_t)(n0 + row) * K + k0 + u * 8);
    }
}

template <int MODE>   // 0: fp16 out; 1: fused conv -> fp32 out
__global__ __launch_bounds__(256, 1)
void gemm_mma(const f16* __restrict__ A, const f16* __restrict__ B,
              const float* __restrict__ bias,
              f16* __restrict__ Ch, float* __restrict__ Cf,
              const float* __restrict__ wc1, const float* __restrict__ bc1,
              const float* __restrict__ wc2, const float* __restrict__ bc2,
              int M, int N, int K) {
    extern __shared__ __align__(128) char smem[];
    const uint32_t sbase = smem_u32(smem);
    const int tid = threadIdx.x;
    const int wid = tid >> 5;
    const int lane = tid & 31;
    const int warp_m = wid >> 1;           // 0..3 -> 64-row slice
    const int warp_n = wid & 1;            // 0..1 -> 64-col slice
    const int m0 = blockIdx.y * BMT;
    const int n0 = blockIdx.x * BNT;

    float acc[4][8][4];
#pragma unroll
    for (int a = 0; a < 4; ++a)
#pragma unroll
        for (int b = 0; b < 8; ++b)
#pragma unroll
            for (int d = 0; d < 4; ++d) acc[a][b][d] = 0.0f;

    const int aRow = warp_m * 64 + (lane & 7) + (((lane >> 3) & 1) << 3);
    const int aUsel = lane >> 4;           // 0/1
    const int bRow = warp_n * 64 + ((lane >> 4) << 3) + (lane & 7);
    const int bUsel = (lane >> 3) & 1;     // 0/1

    const int T = K / BKT;
    load_stage(sbase, A, B, m0, n0, 0, K, tid);
    cp_commit();
    load_stage(sbase + STAGE_BYTES, A, B, m0, n0, BKT, K, tid);
    cp_commit();
    load_stage(sbase + 2 * STAGE_BYTES, A, B, m0, n0, 2 * BKT, K, tid);
    cp_commit();

    for (int t = 0; t < T; ++t) {
        if (t + 2 < T)      cp_wait<2>();
        else if (t + 1 < T) cp_wait<1>();
        else                cp_wait<0>();
        __syncthreads();   // the ONLY barrier per tile

        // loads for stage t+3 target buffer (t+3)&3 == (t-1)&3, drained above
        if (t + 3 < T) {
            load_stage(sbase + ((t + 3) & 3) * STAGE_BYTES, A, B,
                       m0, n0, (t + 3) * BKT, K, tid);
            cp_commit();
        }

        const uint32_t aB = sbase + (t & 3) * STAGE_BYTES;
        const uint32_t bB = aB + A_BYTES;

#pragma unroll
        for (int kk = 0; kk < 4; ++kk) {   // 4 x K=16 steps
            uint32_t ah[4][4];
#pragma unroll
            for (int mf = 0; mf < 4; ++mf) {
                const int m = aRow + mf * 16;
                const int u = kk * 2 + aUsel;
                ldsm_x4(aB + m * ROWB + u * 16, ah[mf]);
            }
#pragma unroll
            for (int nfp = 0; nfp < 4; ++nfp) {
                const int n = bRow + nfp * 16;
                const int u = kk * 2 + bUsel;
                uint32_t bh[4];
                ldsm_x4(bB + n * ROWB + u * 16, bh);   // [n][k] == col-major B
#pragma unroll
                for (int mf = 0; mf < 4; ++mf) {
                    mma16816(acc[mf][2 * nfp],     ah[mf], bh);
                    mma16816(acc[mf][2 * nfp + 1], ah[mf], bh + 2);
                }
            }
        }
    }

    // ----------------- epilogue ---------------------------------------------
    const int gid = lane >> 2, tg = lane & 3;
    float cw10 = 0.f, cw11 = 0.f, cw20 = 0.f, cw21 = 0.f, cb1 = 0.f, cb2 = 0.f;
    if (MODE == 1) {
        cw10 = wc1[0]; cw11 = wc1[1];
        cw20 = wc2[0]; cw21 = wc2[1];
        cb1 = bc1[0];  cb2 = bc2[0];
    }
#pragma unroll
    for (int mf = 0; mf < 4; ++mf) {
#pragma unroll
        for (int nf = 0; nf < 8; ++nf) {
            const int row0 = m0 + warp_m * 64 + mf * 16 + gid;
            const int col = n0 + warp_n * 64 + nf * 8 + tg * 2;
            const float bv0 = bias[col], bv1 = bias[col + 1];
            const float* a4 = acc[mf][nf];
            const float v00 = tanhf(a4[0] + bv0);
            const float v01 = tanhf(a4[1] + bv1);
            const float v10 = tanhf(a4[2] + bv0);
            const float v11 = tanhf(a4[3] + bv1);
            if (MODE == 0) {
                uint32_t* ChW = (uint32_t*)Ch;
                ChW[(size_t)row0 * (N >> 1) + (col >> 1)]       = pack_h2(v00, v01);
                ChW[(size_t)(row0 + 8) * (N >> 1) + (col >> 1)] = pack_h2(v10, v11);
            } else {
                // conv1 over this thread's own (col, col+1) pair
                const float t0 = tanhf(fmaf(v00, cw10, fmaf(v01, cw11, cb1)));
                const float t1 = tanhf(fmaf(v10, cw10, fmaf(v11, cw11, cb1)));
                // conv2 pairs conv1 outputs of tg and tg^1
                const float p0 = __shfl_xor_sync(0xFFFFFFFFu, t0, 1);
                const float p1 = __shfl_xor_sync(0xFFFFFFFFu, t1, 1);
                if ((tg & 1) == 0) {
                    const int j2 = (n0 >> 2) + warp_n * 16 + nf * 2 + (tg >> 1);
                    Cf[(size_t)row0 * OUT_DIM + j2] =
                        tanhf(fmaf(t0, cw20, fmaf(p0, cw21, cb2)));
                    Cf[(size_t)(row0 + 8) * OUT_DIM + j2] =
                        tanhf(fmaf(t1, cw20, fmaf(p1, cw21, cb2)));
                }
            }
        }
    }
}

// ------------------------- launch ------------------------------------------
extern "C" void kernel_launch(void* const* d_in, const int* in_sizes, int n_in,
                              void* d_out, int out_size) {
    const float* x       = (const float*)d_in[0];
    const void*  mask_ih = d_in[1];
    const void*  mask_hc = d_in[2];
    const float* w_ih    = (const float*)d_in[3];
    const float* b_ih    = (const float*)d_in[4];
    const float* w_hc    = (const float*)d_in[5];
    const float* b_hc    = (const float*)d_in[6];
    const float* w_c1    = (const float*)d_in[7];
    const float* b_c1    = (const float*)d_in[8];
    const float* w_c2    = (const float*)d_in[9];
    const float* b_c2    = (const float*)d_in[10];
    float* out = (float*)d_out;

    f16 *xh, *w1, *h, *w2;
    int* mode;
    cudaGetSymbolAddress((void**)&xh, g_x);
    cudaGetSymbolAddress((void**)&w1, g_w1);
    cudaGetSymbolAddress((void**)&h, g_h);
    cudaGetSymbolAddress((void**)&w2, g_w2);
    cudaGetSymbolAddress((void**)&mode, g_mask_mode);

    cudaFuncSetAttribute(gemm_mma<0>, cudaFuncAttributeMaxDynamicSharedMemorySize, SMEM_GEMM);
    cudaFuncSetAttribute(gemm_mma<1>, cudaFuncAttributeMaxDynamicSharedMemorySize, SMEM_GEMM);

    // 0) mask dtype detection
    detect_mask_mode<<<1, 1>>>((const uint32_t*)mask_ih, mode + 0);
    detect_mask_mode<<<1, 1>>>((const uint32_t*)mask_hc, mode + 1);

    // 1) preps: x -> fp16; masked w1/w2 -> fp16
    {
        size_t n4 = (size_t)BATCH * IN_DIM / 4;
        prep_x_f16<<<(unsigned)((n4 + 255) / 256), 256>>>(x, xh, n4);
    }
    {
        size_t n4 = (size_t)HID_DIM * IN_DIM / 4;
        prep_w_f16<<<(unsigned)((n4 + 255) / 256), 256>>>(w_ih, mask_ih, mode + 0, w1, n4);
    }
    {
        size_t n4 = (size_t)CNV_DIM * HID_DIM / 4;
        prep_w_f16<<<(unsigned)((n4 + 255) / 256), 256>>>(w_hc, mask_hc, mode + 1, w2, n4);
    }

    // 2) h = tanh(x @ w1^T + b_ih) -> fp16
    {
        dim3 grid(HID_DIM / BNT, BATCH / BMT);   // (16, 64)
        gemm_mma<0><<<grid, 256, SMEM_GEMM>>>(xh, w1, b_ih, h, nullptr,
                                              nullptr, nullptr, nullptr, nullptr,
                                              BATCH, HID_DIM, IN_DIM);
    }

    // 3) out = tanh(conv2(tanh(conv1(tanh(h @ w2^T + b_hc)))))  (fused)
    {
        dim3 grid(CNV_DIM / BNT, BATCH / BMT);   // (8, 64)
        gemm_mma<1><<<grid, 256, SMEM_GEMM>>>(h, w2, b_hc, nullptr, out,
                                              w_c1, b_c1, w_c2, b_c2,
                                              BATCH, CNV_DIM, HID_DIM);
    }
}

// round 16
// speedup vs baseline: 1.5007x; 1.0253x over previous
#include <cuda_runtime.h>
#include <cuda_fp16.h>
#include <math.h>
#include <stdint.h>

// ---------------------------------------------------------------------------
// MPWEncoder via mma.sync — fp16 GEMMs (fp32 accum). 256x128 block, BKT=64,
// 16 warps (warp tile 64x32) -> 4 warps/SMSP for latency hiding, 4-stage
// cp.async pipeline w/ one barrier per k-tile. Double conv fused in GEMM2.
// Dims: BATCH=16384, IN=4096, HID=2048, CNV1=1024, out [16384, 256]
// ---------------------------------------------------------------------------
#define BATCH   16384
#define IN_DIM  4096
#define HID_DIM 2048
#define CNV_DIM 1024
#define OUT_DIM 256

typedef __half f16;

// ------------------------- device scratch (no allocs) ----------------------
__device__ __align__(1024) f16 g_x [(size_t)BATCH * IN_DIM];
__device__ __align__(1024) f16 g_w1[(size_t)HID_DIM * IN_DIM];
__device__ __align__(1024) f16 g_h [(size_t)BATCH * HID_DIM];
__device__ __align__(1024) f16 g_w2[(size_t)CNV_DIM * HID_DIM];
__device__ int g_mask_mode[2];

// ------------------------- PTX helpers -------------------------------------
__device__ __forceinline__ uint32_t smem_u32(const void* p) {
    uint32_t a;
    asm("{ .reg .u64 t; cvta.to.shared.u64 t, %1; cvt.u32.u64 %0, t; }"
        : "=r"(a) : "l"(p));
    return a;
}
__device__ __forceinline__ void cp16(uint32_t dst, const void* src) {
    asm volatile("cp.async.cg.shared.global [%0], [%1], 16;" :: "r"(dst), "l"(src));
}
__device__ __forceinline__ void cp_commit() {
    asm volatile("cp.async.commit_group;" ::: "memory");
}
template <int N>
__device__ __forceinline__ void cp_wait() {
    asm volatile("cp.async.wait_group %0;" :: "n"(N) : "memory");
}
__device__ __forceinline__ void ldsm_x4(uint32_t addr, uint32_t* r) {
    asm volatile("ldmatrix.sync.aligned.m8n8.x4.shared.b16 {%0,%1,%2,%3}, [%4];"
                 : "=r"(r[0]), "=r"(r[1]), "=r"(r[2]), "=r"(r[3]) : "r"(addr));
}
__device__ __forceinline__ void mma16816(float* c, const uint32_t* a, const uint32_t* b) {
    asm volatile(
        "mma.sync.aligned.m16n8k16.row.col.f32.f16.f16.f32 "
        "{%0,%1,%2,%3}, {%4,%5,%6,%7}, {%8,%9}, {%0,%1,%2,%3};"
        : "+f"(c[0]), "+f"(c[1]), "+f"(c[2]), "+f"(c[3])
        : "r"(a[0]), "r"(a[1]), "r"(a[2]), "r"(a[3]), "r"(b[0]), "r"(b[1]));
}

// ------------------------- mask detection + preps ---------------------------
__global__ void detect_mask_mode(const uint32_t* __restrict__ m, int* __restrict__ mode) {
    int floatish = 0, all01 = 1;
    for (int i = 0; i < 256; ++i) {
        uint32_t w = m[i];
        if (w == 0x3F800000u) floatish = 1;
        if (w > 1u) all01 = 0;
    }
    *mode = floatish ? 2 : (all01 ? 1 : 0);
}

__device__ __forceinline__ uint32_t pack_h2(float a, float b) {
    __half2 t = __floats2half2_rn(a, b);
    return *reinterpret_cast<uint32_t*>(&t);
}

__global__ void prep_x_f16(const float* __restrict__ x, f16* __restrict__ out, size_t n4) {
    size_t i = (size_t)blockIdx.x * blockDim.x + threadIdx.x;
    if (i >= n4) return;
    float4 v = ((const float4*)x)[i];
    uint2 o;
    o.x = pack_h2(v.x, v.y);
    o.y = pack_h2(v.z, v.w);
    ((uint2*)out)[i] = o;
}

__global__ void prep_w_f16(const float* __restrict__ w, const void* __restrict__ mask,
                           const int* __restrict__ mode_p,
                           f16* __restrict__ out, size_t n4) {
    size_t i = (size_t)blockIdx.x * blockDim.x + threadIdx.x;
    if (i >= n4) return;
    const int mode = *mode_p;
    float4 v = ((const float4*)w)[i];
    bool m0, m1, m2, m3;
    if (mode == 0) {
        uchar4 mm = ((const uchar4*)mask)[i];
        m0 = mm.x; m1 = mm.y; m2 = mm.z; m3 = mm.w;
    } else if (mode == 1) {
        int4 mm = ((const int4*)mask)[i];
        m0 = mm.x; m1 = mm.y; m2 = mm.z; m3 = mm.w;
    } else {
        float4 mm = ((const float4*)mask)[i];
        m0 = mm.x != 0.f; m1 = mm.y != 0.f; m2 = mm.z != 0.f; m3 = mm.w != 0.f;
    }
    uint2 o;
    o.x = pack_h2(m0 ? v.x : 0.f, m1 ? v.y : 0.f);
    o.y = pack_h2(m2 ? v.z : 0.f, m3 ? v.w : 0.f);
    ((uint2*)out)[i] = o;
}

// ------------------------- mma.sync GEMM ------------------------------------
// C[M,N] = tanh(A[M,K] @ B[N,K]^T + bias[N]); A,B fp16, fp32 accumulate.
// Block tile 256x128x64, 16 warps (warp tile 64x32: warp_m=wid>>2,
// warp_n=wid&3), 4-stage cp.async pipeline, ONE __syncthreads per k-tile.
// ROWB=144 -> conflict-free ldsm without XOR swizzle.
// MODE 0: fp16 C out.  MODE 1: fused double conv1d(k2,s2)+tanh -> fp32 out.
#define BMT 256
#define BNT 128
#define BKT 64
#define NTHR 512
#define ROWB 144                           // 128B data + 16B pad per row
#define A_BYTES (BMT * ROWB)               // 36864
#define B_BYTES (BNT * ROWB)               // 18432
#define STAGE_BYTES (A_BYTES + B_BYTES)    // 55296
#define NSTAGE 4
#define SMEM_GEMM (NSTAGE * STAGE_BYTES)   // 221184

__device__ __forceinline__ void load_stage(uint32_t sb,
                                           const f16* A, const f16* B,
                                           int m0, int n0, int k0, int K, int tid) {
#pragma unroll
    for (int i = 0; i < 4; ++i) {          // A: 256 rows x 8 16B-chunks (2048)
        const int ch = tid + (i << 9);
        const int row = ch >> 3, u = ch & 7;
        cp16(sb + row * ROWB + u * 16, A + (size_t)(m0 + row) * K + k0 + u * 8);
    }
#pragma unroll
    for (int i = 0; i < 2; ++i) {          // B: 128 rows x 8 16B-chunks (1024)
        const int ch = tid + (i << 9);
        const int row = ch >> 3, u = ch & 7;
        cp16(sb + A_BYTES + row * ROWB + u * 16, B + (size_t)(n0 + row) * K + k0 + u * 8);
    }
}

template <int MODE>   // 0: fp16 out; 1: fused conv -> fp32 out
__global__ __launch_bounds__(NTHR, 1)
void gemm_mma(const f16* __restrict__ A, const f16* __restrict__ B,
              const float* __restrict__ bias,
              f16* __restrict__ Ch, float* __restrict__ Cf,
              const float* __restrict__ wc1, const float* __restrict__ bc1,
              const float* __restrict__ wc2, const float* __restrict__ bc2,
              int M, int N, int K) {
    extern __shared__ __align__(128) char smem[];
    const uint32_t sbase = smem_u32(smem);
    const int tid = threadIdx.x;
    const int wid = tid >> 5;
    const int lane = tid & 31;
    const int warp_m = wid >> 2;           // 0..3 -> 64-row slice
    const int warp_n = wid & 3;            // 0..3 -> 32-col slice
    const int m0 = blockIdx.y * BMT;
    const int n0 = blockIdx.x * BNT;

    float acc[4][4][4];
#pragma unroll
    for (int a = 0; a < 4; ++a)
#pragma unroll
        for (int b = 0; b < 4; ++b)
#pragma unroll
            for (int d = 0; d < 4; ++d) acc[a][b][d] = 0.0f;

    const int aRow = warp_m * 64 + (lane & 7) + (((lane >> 3) & 1) << 3);
    const int aUsel = lane >> 4;           // 0/1
    const int bRow = warp_n * 32 + ((lane >> 4) << 3) + (lane & 7);
    const int bUsel = (lane >> 3) & 1;     // 0/1

    const int T = K / BKT;
    load_stage(sbase, A, B, m0, n0, 0, K, tid);
    cp_commit();
    load_stage(sbase + STAGE_BYTES, A, B, m0, n0, BKT, K, tid);
    cp_commit();
    load_stage(sbase + 2 * STAGE_BYTES, A, B, m0, n0, 2 * BKT, K, tid);
    cp_commit();

    for (int t = 0; t < T; ++t) {
        if (t + 2 < T)      cp_wait<2>();
        else if (t + 1 < T) cp_wait<1>();
        else                cp_wait<0>();
        __syncthreads();   // the ONLY barrier per tile

        // loads for stage t+3 target buffer (t+3)&3 == (t-1)&3, drained above
        if (t + 3 < T) {
            load_stage(sbase + ((t + 3) & 3) * STAGE_BYTES, A, B,
                       m0, n0, (t + 3) * BKT, K, tid);
            cp_commit();
        }

        const uint32_t aB = sbase + (t & 3) * STAGE_BYTES;
        const uint32_t bB = aB + A_BYTES;

#pragma unroll
        for (int kk = 0; kk < 4; ++kk) {   // 4 x K=16 steps
            uint32_t ah[4][4];
#pragma unroll
            for (int mf = 0; mf < 4; ++mf) {
                const int m = aRow + mf * 16;
                const int u = kk * 2 + aUsel;
                ldsm_x4(aB + m * ROWB + u * 16, ah[mf]);
            }
#pragma unroll
            for (int nfp = 0; nfp < 2; ++nfp) {
                const int n = bRow + nfp * 16;
                const int u = kk * 2 + bUsel;
                uint32_t bh[4];
                ldsm_x4(bB + n * ROWB + u * 16, bh);   // [n][k] == col-major B
#pragma unroll
                for (int mf = 0; mf < 4; ++mf) {
                    mma16816(acc[mf][2 * nfp],     ah[mf], bh);
                    mma16816(acc[mf][2 * nfp + 1], ah[mf], bh + 2);
                }
            }
        }
    }

    // ----------------- epilogue ---------------------------------------------
    const int gid = lane >> 2, tg = lane & 3;
    float cw10 = 0.f, cw11 = 0.f, cw20 = 0.f, cw21 = 0.f, cb1 = 0.f, cb2 = 0.f;
    if (MODE == 1) {
        cw10 = wc1[0]; cw11 = wc1[1];
        cw20 = wc2[0]; cw21 = wc2[1];
        cb1 = bc1[0];  cb2 = bc2[0];
    }
#pragma unroll
    for (int mf = 0; mf < 4; ++mf) {
#pragma unroll
        for (int nf = 0; nf < 4; ++nf) {
            const int row0 = m0 + warp_m * 64 + mf * 16 + gid;
            const int col = n0 + warp_n * 32 + nf * 8 + tg * 2;
            const float bv0 = bias[col], bv1 = bias[col + 1];
            const float* a4 = acc[mf][nf];
            const float v00 = tanhf(a4[0] + bv0);
            const float v01 = tanhf(a4[1] + bv1);
            const float v10 = tanhf(a4[2] + bv0);
            const float v11 = tanhf(a4[3] + bv1);
            if (MODE == 0) {
                uint32_t* ChW = (uint32_t*)Ch;
                ChW[(size_t)row0 * (N >> 1) + (col >> 1)]       = pack_h2(v00, v01);
                ChW[(size_t)(row0 + 8) * (N >> 1) + (col >> 1)] = pack_h2(v10, v11);
            } else {
                // conv1 over this thread's own (col, col+1) pair
                const float t0 = tanhf(fmaf(v00, cw10, fmaf(v01, cw11, cb1)));
                const float t1 = tanhf(fmaf(v10, cw10, fmaf(v11, cw11, cb1)));
                // conv2 pairs conv1 outputs of tg and tg^1
                const float p0 = __shfl_xor_sync(0xFFFFFFFFu, t0, 1);
                const float p1 = __shfl_xor_sync(0xFFFFFFFFu, t1, 1);
                if ((tg & 1) == 0) {
                    const int j2 = (n0 >> 2) + warp_n * 8 + nf * 2 + (tg >> 1);
                    Cf[(size_t)row0 * OUT_DIM + j2] =
                        tanhf(fmaf(t0, cw20, fmaf(p0, cw21, cb2)));
                    Cf[(size_t)(row0 + 8) * OUT_DIM + j2] =
                        tanhf(fmaf(t1, cw20, fmaf(p1, cw21, cb2)));
                }
            }
        }
    }
}

// ------------------------- launch ------------------------------------------
extern "C" void kernel_launch(void* const* d_in, const int* in_sizes, int n_in,
                              void* d_out, int out_size) {
    const float* x       = (const float*)d_in[0];
    const void*  mask_ih = d_in[1];
    const void*  mask_hc = d_in[2];
    const float* w_ih    = (const float*)d_in[3];
    const float* b_ih    = (const float*)d_in[4];
    const float* w_hc    = (const float*)d_in[5];
    const float* b_hc    = (const float*)d_in[6];
    const float* w_c1    = (const float*)d_in[7];
    const float* b_c1    = (const float*)d_in[8];
    const float* w_c2    = (const float*)d_in[9];
    const float* b_c2    = (const float*)d_in[10];
    float* out = (float*)d_out;

    f16 *xh, *w1, *h, *w2;
    int* mode;
    cudaGetSymbolAddress((void**)&xh, g_x);
    cudaGetSymbolAddress((void**)&w1, g_w1);
    cudaGetSymbolAddress((void**)&h, g_h);
    cudaGetSymbolAddress((void**)&w2, g_w2);
    cudaGetSymbolAddress((void**)&mode, g_mask_mode);

    cudaFuncSetAttribute(gemm_mma<0>, cudaFuncAttributeMaxDynamicSharedMemorySize, SMEM_GEMM);
    cudaFuncSetAttribute(gemm_mma<1>, cudaFuncAttributeMaxDynamicSharedMemorySize, SMEM_GEMM);

    // 0) mask dtype detection
    detect_mask_mode<<<1, 1>>>((const uint32_t*)mask_ih, mode + 0);
    detect_mask_mode<<<1, 1>>>((const uint32_t*)mask_hc, mode + 1);

    // 1) preps: x -> fp16; masked w1/w2 -> fp16
    {
        size_t n4 = (size_t)BATCH * IN_DIM / 4;
        prep_x_f16<<<(unsigned)((n4 + 255) / 256), 256>>>(x, xh, n4);
    }
    {
        size_t n4 = (size_t)HID_DIM * IN_DIM / 4;
        prep_w_f16<<<(unsigned)((n4 + 255) / 256), 256>>>(w_ih, mask_ih, mode + 0, w1, n4);
    }
    {
        size_t n4 = (size_t)CNV_DIM * HID_DIM / 4;
        prep_w_f16<<<(unsigned)((n4 + 255) / 256), 256>>>(w_hc, mask_hc, mode + 1, w2, n4);
    }

    // 2) h = tanh(x @ w1^T + b_ih) -> fp16
    {
        dim3 grid(HID_DIM / BNT, BATCH / BMT);   // (16, 64)
        gemm_mma<0><<<grid, NTHR, SMEM_GEMM>>>(xh, w1, b_ih, h, nullptr,
                                               nullptr, nullptr, nullptr, nullptr,
                                               BATCH, HID_DIM, IN_DIM);
    }

    // 3) out = tanh(conv2(tanh(conv1(tanh(h @ w2^T + b_hc)))))  (fused)
    {
        dim3 grid(CNV_DIM / BNT, BATCH / BMT);   // (8, 64)
        gemm_mma<1><<<grid, NTHR, SMEM_GEMM>>>(h, w2, b_hc, nullptr, out,
                                               w_c1, b_c1, w_c2, b_c2,
                                               BATCH, CNV_DIM, HID_DIM);
    }
}

// round 17
// speedup vs baseline: 1.5385x; 1.0252x over previous
#include <cuda_runtime.h>
#include <cuda_fp16.h>
#include <math.h>
#include <stdint.h>

// ---------------------------------------------------------------------------
// MPWEncoder via mma.sync — fp16 GEMMs (fp32 accum), at the legacy-HMMA
// issue-rate wall. 256x128x64 block, 16 warps (64x32 warp tile), 4-stage
// cp.async pipeline, 1 barrier/tile, conv1d x2 fused in GEMM2 epilogue.
// This round: single fused prep kernel + parallel mask-dtype detect.
// Dims: BATCH=16384, IN=4096, HID=2048, CNV1=1024, out [16384, 256]
// ---------------------------------------------------------------------------
#define BATCH   16384
#define IN_DIM  4096
#define HID_DIM 2048
#define CNV_DIM 1024
#define OUT_DIM 256

typedef __half f16;

// ------------------------- device scratch (no allocs) ----------------------
__device__ __align__(1024) f16 g_x [(size_t)BATCH * IN_DIM];
__device__ __align__(1024) f16 g_w1[(size_t)HID_DIM * IN_DIM];
__device__ __align__(1024) f16 g_h [(size_t)BATCH * HID_DIM];
__device__ __align__(1024) f16 g_w2[(size_t)CNV_DIM * HID_DIM];
__device__ int g_mask_mode[2];

// ------------------------- PTX helpers -------------------------------------
__device__ __forceinline__ uint32_t smem_u32(const void* p) {
    uint32_t a;
    asm("{ .reg .u64 t; cvta.to.shared.u64 t, %1; cvt.u32.u64 %0, t; }"
        : "=r"(a) : "l"(p));
    return a;
}
__device__ __forceinline__ void cp16(uint32_t dst, const void* src) {
    asm volatile("cp.async.cg.shared.global [%0], [%1], 16;" :: "r"(dst), "l"(src));
}
__device__ __forceinline__ void cp_commit() {
    asm volatile("cp.async.commit_group;" ::: "memory");
}
template <int N>
__device__ __forceinline__ void cp_wait() {
    asm volatile("cp.async.wait_group %0;" :: "n"(N) : "memory");
}
__device__ __forceinline__ void ldsm_x4(uint32_t addr, uint32_t* r) {
    asm volatile("ldmatrix.sync.aligned.m8n8.x4.shared.b16 {%0,%1,%2,%3}, [%4];"
                 : "=r"(r[0]), "=r"(r[1]), "=r"(r[2]), "=r"(r[3]) : "r"(addr));
}
__device__ __forceinline__ void mma16816(float* c, const uint32_t* a, const uint32_t* b) {
    asm volatile(
        "mma.sync.aligned.m16n8k16.row.col.f32.f16.f16.f32 "
        "{%0,%1,%2,%3}, {%4,%5,%6,%7}, {%8,%9}, {%0,%1,%2,%3};"
        : "+f"(c[0]), "+f"(c[1]), "+f"(c[2]), "+f"(c[3])
        : "r"(a[0]), "r"(a[1]), "r"(a[2]), "r"(a[3]), "r"(b[0]), "r"(b[1]));
}

// ------------------------- mask detection (parallel, 1 launch) --------------
__global__ void detect_mask_modes(const uint32_t* __restrict__ m0,
                                  const uint32_t* __restrict__ m1,
                                  int* __restrict__ modes) {
    const uint32_t* m = blockIdx.x ? m1 : m0;
    const uint32_t w = m[threadIdx.x];
    const int anyf = __syncthreads_or(w == 0x3F800000u);
    const int anyn = __syncthreads_or(w > 1u);
    if (threadIdx.x == 0) modes[blockIdx.x] = anyf ? 2 : (anyn ? 0 : 1);
}

// ------------------------- fused prep (x, w1, w2 in one launch) -------------
__device__ __forceinline__ uint32_t pack_h2(float a, float b) {
    __half2 t = __floats2half2_rn(a, b);
    return *reinterpret_cast<uint32_t*>(&t);
}

// one 8-element chunk: 2x float4 in -> uint4 (8 halves) out
__device__ __forceinline__ uint4 cvt8(float4 a, float4 b) {
    uint4 o;
    o.x = pack_h2(a.x, a.y);
    o.y = pack_h2(a.z, a.w);
    o.z = pack_h2(b.x, b.y);
    o.w = pack_h2(b.z, b.w);
    return o;
}

__device__ __forceinline__ void mask8(const void* mask, int mode, size_t j,
                                      float4& a, float4& b) {
    if (mode == 0) {
        uchar4 ma = ((const uchar4*)mask)[2 * j];
        uchar4 mb = ((const uchar4*)mask)[2 * j + 1];
        if (!ma.x) a.x = 0.f; if (!ma.y) a.y = 0.f;
        if (!ma.z) a.z = 0.f; if (!ma.w) a.w = 0.f;
        if (!mb.x) b.x = 0.f; if (!mb.y) b.y = 0.f;
        if (!mb.z) b.z = 0.f; if (!mb.w) b.w = 0.f;
    } else if (mode == 1) {
        int4 ma = ((const int4*)mask)[2 * j];
        int4 mb = ((const int4*)mask)[2 * j + 1];
        if (!ma.x) a.x = 0.f; if (!ma.y) a.y = 0.f;
        if (!ma.z) a.z = 0.f; if (!ma.w) a.w = 0.f;
        if (!mb.x) b.x = 0.f; if (!mb.y) b.y = 0.f;
        if (!mb.z) b.z = 0.f; if (!mb.w) b.w = 0.f;
    } else {
        float4 ma = ((const float4*)mask)[2 * j];
        float4 mb = ((const float4*)mask)[2 * j + 1];
        if (ma.x == 0.f) a.x = 0.f; if (ma.y == 0.f) a.y = 0.f;
        if (ma.z == 0.f) a.z = 0.f; if (ma.w == 0.f) a.w = 0.f;
        if (mb.x == 0.f) b.x = 0.f; if (mb.y == 0.f) b.y = 0.f;
        if (mb.z == 0.f) b.z = 0.f; if (mb.w == 0.f) b.w = 0.f;
    }
}

#define NX8  ((size_t)BATCH * IN_DIM / 8)     // 8,388,608
#define NW18 ((size_t)HID_DIM * IN_DIM / 8)   // 1,048,576
#define NW28 ((size_t)CNV_DIM * HID_DIM / 8)  //   262,144
#define NPREP (NX8 + NW18 + NW28)

__global__ void prep_all(const float* __restrict__ x,
                         const float* __restrict__ w_ih, const void* __restrict__ m_ih,
                         const float* __restrict__ w_hc, const void* __restrict__ m_hc,
                         const int* __restrict__ modes,
                         f16* __restrict__ xo, f16* __restrict__ w1o,
                         f16* __restrict__ w2o) {
    size_t i = (size_t)blockIdx.x * blockDim.x + threadIdx.x;
    if (i >= NPREP) return;
    if (i < NX8) {
        float4 a = ((const float4*)x)[2 * i];
        float4 b = ((const float4*)x)[2 * i + 1];
        ((uint4*)xo)[i] = cvt8(a, b);
    } else if (i < NX8 + NW18) {
        const size_t j = i - NX8;
        float4 a = ((const float4*)w_ih)[2 * j];
        float4 b = ((const float4*)w_ih)[2 * j + 1];
        mask8(m_ih, modes[0], j, a, b);
        ((uint4*)w1o)[j] = cvt8(a, b);
    } else {
        const size_t j = i - NX8 - NW18;
        float4 a = ((const float4*)w_hc)[2 * j];
        float4 b = ((const float4*)w_hc)[2 * j + 1];
        mask8(m_hc, modes[1], j, a, b);
        ((uint4*)w2o)[j] = cvt8(a, b);
    }
}

// ------------------------- mma.sync GEMM ------------------------------------
// C[M,N] = tanh(A[M,K] @ B[N,K]^T + bias[N]); A,B fp16, fp32 accumulate.
// Block tile 256x128x64, 16 warps (warp tile 64x32), 4-stage cp.async
// pipeline, ONE __syncthreads per k-tile. ROWB=144 -> conflict-free ldsm.
// MODE 0: fp16 C out.  MODE 1: fused double conv1d(k2,s2)+tanh -> fp32 out.
#define BMT 256
#define BNT 128
#define BKT 64
#define NTHR 512
#define ROWB 144                           // 128B data + 16B pad per row
#define A_BYTES (BMT * ROWB)               // 36864
#define B_BYTES (BNT * ROWB)               // 18432
#define STAGE_BYTES (A_BYTES + B_BYTES)    // 55296
#define NSTAGE 4
#define SMEM_GEMM (NSTAGE * STAGE_BYTES)   // 221184

__device__ __forceinline__ void load_stage(uint32_t sb,
                                           const f16* A, const f16* B,
                                           int m0, int n0, int k0, int K, int tid) {
#pragma unroll
    for (int i = 0; i < 4; ++i) {          // A: 256 rows x 8 16B-chunks (2048)
        const int ch = tid + (i << 9);
        const int row = ch >> 3, u = ch & 7;
        cp16(sb + row * ROWB + u * 16, A + (size_t)(m0 + row) * K + k0 + u * 8);
    }
#pragma unroll
    for (int i = 0; i < 2; ++i) {          // B: 128 rows x 8 16B-chunks (1024)
        const int ch = tid + (i << 9);
        const int row = ch >> 3, u = ch & 7;
        cp16(sb + A_BYTES + row * ROWB + u * 16, B + (size_t)(n0 + row) * K + k0 + u * 8);
    }
}

template <int MODE>   // 0: fp16 out; 1: fused conv -> fp32 out
__global__ __launch_bounds__(NTHR, 1)
void gemm_mma(const f16* __restrict__ A, const f16* __restrict__ B,
              const float* __restrict__ bias,
              f16* __restrict__ Ch, float* __restrict__ Cf,
              const float* __restrict__ wc1, const float* __restrict__ bc1,
              const float* __restrict__ wc2, const float* __restrict__ bc2,
              int M, int N, int K) {
    extern __shared__ __align__(128) char smem[];
    const uint32_t sbase = smem_u32(smem);
    const int tid = threadIdx.x;
    const int wid = tid >> 5;
    const int lane = tid & 31;
    const int warp_m = wid >> 2;           // 0..3 -> 64-row slice
    const int warp_n = wid & 3;            // 0..3 -> 32-col slice
    const int m0 = blockIdx.y * BMT;
    const int n0 = blockIdx.x * BNT;

    float acc[4][4][4];
#pragma unroll
    for (int a = 0; a < 4; ++a)
#pragma unroll
        for (int b = 0; b < 4; ++b)
#pragma unroll
            for (int d = 0; d < 4; ++d) acc[a][b][d] = 0.0f;

    const int aRow = warp_m * 64 + (lane & 7) + (((lane >> 3) & 1) << 3);
    const int aUsel = lane >> 4;           // 0/1
    const int bRow = warp_n * 32 + ((lane >> 4) << 3) + (lane & 7);
    const int bUsel = (lane >> 3) & 1;     // 0/1

    const int T = K / BKT;
    load_stage(sbase, A, B, m0, n0, 0, K, tid);
    cp_commit();
    load_stage(sbase + STAGE_BYTES, A, B, m0, n0, BKT, K, tid);
    cp_commit();
    load_stage(sbase + 2 * STAGE_BYTES, A, B, m0, n0, 2 * BKT, K, tid);
    cp_commit();

    for (int t = 0; t < T; ++t) {
        if (t + 2 < T)      cp_wait<2>();
        else if (t + 1 < T) cp_wait<1>();
        else                cp_wait<0>();
        __syncthreads();   // the ONLY barrier per tile

        // loads for stage t+3 target buffer (t+3)&3 == (t-1)&3, drained above
        if (t + 3 < T) {
            load_stage(sbase + ((t + 3) & 3) * STAGE_BYTES, A, B,
                       m0, n0, (t + 3) * BKT, K, tid);
            cp_commit();
        }

        const uint32_t aB = sbase + (t & 3) * STAGE_BYTES;
        const uint32_t bB = aB + A_BYTES;

#pragma unroll
        for (int kk = 0; kk < 4; ++kk) {   // 4 x K=16 steps
            uint32_t ah[4][4];
#pragma unroll
            for (int mf = 0; mf < 4; ++mf) {
                const int m = aRow + mf * 16;
                const int u = kk * 2 + aUsel;
                ldsm_x4(aB + m * ROWB + u * 16, ah[mf]);
            }
#pragma unroll
            for (int nfp = 0; nfp < 2; ++nfp) {
                const int n = bRow + nfp * 16;
                const int u = kk * 2 + bUsel;
                uint32_t bh[4];
                ldsm_x4(bB + n * ROWB + u * 16, bh);   // [n][k] == col-major B
#pragma unroll
                for (int mf = 0; mf < 4; ++mf) {
                    mma16816(acc[mf][2 * nfp],     ah[mf], bh);
                    mma16816(acc[mf][2 * nfp + 1], ah[mf], bh + 2);
                }
            }
        }
    }

    // ----------------- epilogue ---------------------------------------------
    const int gid = lane >> 2, tg = lane & 3;
    float cw10 = 0.f, cw11 = 0.f, cw20 = 0.f, cw21 = 0.f, cb1 = 0.f, cb2 = 0.f;
    if (MODE == 1) {
        cw10 = wc1[0]; cw11 = wc1[1];
        cw20 = wc2[0]; cw21 = wc2[1];
        cb1 = bc1[0];  cb2 = bc2[0];
    }
#pragma unroll
    for (int mf = 0; mf < 4; ++mf) {
#pragma unroll
        for (int nf = 0; nf < 4; ++nf) {
            const int row0 = m0 + warp_m * 64 + mf * 16 + gid;
            const int col = n0 + warp_n * 32 + nf * 8 + tg * 2;
            const float bv0 = bias[col], bv1 = bias[col + 1];
            const float* a4 = acc[mf][nf];
            const float v00 = tanhf(a4[0] + bv0);
            const float v01 = tanhf(a4[1] + bv1);
            const float v10 = tanhf(a4[2] + bv0);
            const float v11 = tanhf(a4[3] + bv1);
            if (MODE == 0) {
                uint32_t* ChW = (uint32_t*)Ch;
                ChW[(size_t)row0 * (N >> 1) + (col >> 1)]       = pack_h2(v00, v01);
                ChW[(size_t)(row0 + 8) * (N >> 1) + (col >> 1)] = pack_h2(v10, v11);
            } else {
                // conv1 over this thread's own (col, col+1) pair
                const float t0 = tanhf(fmaf(v00, cw10, fmaf(v01, cw11, cb1)));
                const float t1 = tanhf(fmaf(v10, cw10, fmaf(v11, cw11, cb1)));
                // conv2 pairs conv1 outputs of tg and tg^1
                const float p0 = __shfl_xor_sync(0xFFFFFFFFu, t0, 1);
                const float p1 = __shfl_xor_sync(0xFFFFFFFFu, t1, 1);
                if ((tg & 1) == 0) {
                    const int j2 = (n0 >> 2) + warp_n * 8 + nf * 2 + (tg >> 1);
                    Cf[(size_t)row0 * OUT_DIM + j2] =
                        tanhf(fmaf(t0, cw20, fmaf(p0, cw21, cb2)));
                    Cf[(size_t)(row0 + 8) * OUT_DIM + j2] =
                        tanhf(fmaf(t1, cw20, fmaf(p1, cw21, cb2)));
                }
            }
        }
    }
}

// ------------------------- launch ------------------------------------------
extern "C" void kernel_launch(void* const* d_in, const int* in_sizes, int n_in,
                              void* d_out, int out_size) {
    const float* x       = (const float*)d_in[0];
    const void*  mask_ih = d_in[1];
    const void*  mask_hc = d_in[2];
    const float* w_ih    = (const float*)d_in[3];
    const float* b_ih    = (const float*)d_in[4];
    const float* w_hc    = (const float*)d_in[5];
    const float* b_hc    = (const float*)d_in[6];
    const float* w_c1    = (const float*)d_in[7];
    const float* b_c1    = (const float*)d_in[8];
    const float* w_c2    = (const float*)d_in[9];
    const float* b_c2    = (const float*)d_in[10];
    float* out = (float*)d_out;

    f16 *xh, *w1, *h, *w2;
    int* mode;
    cudaGetSymbolAddress((void**)&xh, g_x);
    cudaGetSymbolAddress((void**)&w1, g_w1);
    cudaGetSymbolAddress((void**)&h, g_h);
    cudaGetSymbolAddress((void**)&w2, g_w2);
    cudaGetSymbolAddress((void**)&mode, g_mask_mode);

    cudaFuncSetAttribute(gemm_mma<0>, cudaFuncAttributeMaxDynamicSharedMemorySize, SMEM_GEMM);
    cudaFuncSetAttribute(gemm_mma<1>, cudaFuncAttributeMaxDynamicSharedMemorySize, SMEM_GEMM);

    // 0) mask dtype detection (both masks, one launch)
    detect_mask_modes<<<2, 256>>>((const uint32_t*)mask_ih, (const uint32_t*)mask_hc, mode);

    // 1) fused prep: x -> fp16, masked w1/w2 -> fp16 (one launch)
    {
        const unsigned blocks = (unsigned)((NPREP + 255) / 256);
        prep_all<<<blocks, 256>>>(x, w_ih, mask_ih, w_hc, mask_hc, mode, xh, w1, w2);
    }

    // 2) h = tanh(x @ w1^T + b_ih) -> fp16
    {
        dim3 grid(HID_DIM / BNT, BATCH / BMT);   // (16, 64)
        gemm_mma<0><<<grid, NTHR, SMEM_GEMM>>>(xh, w1, b_ih, h, nullptr,
                                               nullptr, nullptr, nullptr, nullptr,
                                               BATCH, HID_DIM, IN_DIM);
    }

    // 3) out = tanh(conv2(tanh(conv1(tanh(h @ w2^T + b_hc)))))  (fused)
    {
        dim3 grid(CNV_DIM / BNT, BATCH / BMT);   // (8, 64)
        gemm_mma<1><<<grid, NTHR, SMEM_GEMM>>>(h, w2, b_hc, nullptr, out,
                                               w_c1, b_c1, w_c2, b_c2,
                                               BATCH, CNV_DIM, HID_DIM);
    }
}